// round 5
// baseline (speedup 1.0000x reference)
#include <cuda_runtime.h>
#include <cstdint>

#define HN 16
#define DD 64
#define BQ 128
#define BK 64
#define NT 256
#define QSCALE 0.1803368801111f   // (1/8) * log2(e)

// smem BYTE offsets (all 16B aligned)
#define B_K0   0            // K buf 0: [64][68] floats = 17408B
#define B_K1   17408
#define B_V0   34816        // V raw buf 0
#define B_V1   52224
#define B_VT   69632        // V transposed [d][k]
#define B_KSEG 87040        // 64 ints
#define B_CUS  87296        // 64 ints
#define SMEM_BYTES 87552

__device__ __forceinline__ uint32_t f2tf(float x) {
    uint32_t r; asm("cvt.rna.tf32.f32 %0, %1;" : "=r"(r) : "f"(x)); return r;
}
__device__ __forceinline__ float ex2f(float x) {
    float y; asm("ex2.approx.ftz.f32 %0, %1;" : "=f"(y) : "f"(x)); return y;
}
__device__ __forceinline__ void mma8(float* c, const uint32_t* a, uint32_t b0, uint32_t b1) {
    asm volatile("mma.sync.aligned.m16n8k8.row.col.f32.tf32.tf32.f32 "
                 "{%0,%1,%2,%3}, {%4,%5,%6,%7}, {%8,%9}, {%0,%1,%2,%3};"
                 : "+f"(c[0]), "+f"(c[1]), "+f"(c[2]), "+f"(c[3])
                 : "r"(a[0]), "r"(a[1]), "r"(a[2]), "r"(a[3]), "r"(b0), "r"(b1));
}
__device__ __forceinline__ void ldsm4(uint32_t* r, uint32_t addr) {
    asm volatile("ldmatrix.sync.aligned.m8n8.x4.shared.b16 {%0,%1,%2,%3}, [%4];"
                 : "=r"(r[0]), "=r"(r[1]), "=r"(r[2]), "=r"(r[3]) : "r"(addr));
}
__device__ __forceinline__ uint32_t s2u(const void* p) {
    uint32_t a;
    asm("{ .reg .u64 t; cvta.to.shared.u64 t, %1; cvt.u32.u64 %0, t; }" : "=r"(a) : "l"(p));
    return a;
}
__device__ __forceinline__ void cpasync16(uint32_t saddr, const void* gaddr) {
    asm volatile("cp.async.cg.shared.global [%0], [%1], 16;" :: "r"(saddr), "l"(gaddr));
}
#define CP_COMMIT() asm volatile("cp.async.commit_group;" ::: "memory")
#define CP_WAIT0()  asm volatile("cp.async.wait_group 0;" ::: "memory")

// 4x4 transpose among lanes 4a..4a+3 (j = lane&3)
__device__ __forceinline__ void trans4(float4& v, int j) {
    float s0 = (j & 2) ? v.x : v.z;
    float s1 = (j & 2) ? v.y : v.w;
    float r0 = __shfl_xor_sync(0xffffffffu, s0, 2);
    float r1 = __shfl_xor_sync(0xffffffffu, s1, 2);
    if (j & 2) { v.x = r0; v.y = r1; } else { v.z = r0; v.w = r1; }
    s0 = (j & 1) ? v.x : v.y;
    s1 = (j & 1) ? v.z : v.w;
    r0 = __shfl_xor_sync(0xffffffffu, s0, 1);
    r1 = __shfl_xor_sync(0xffffffffu, s1, 1);
    if (j & 1) { v.x = r0; v.z = r1; } else { v.y = r0; v.w = r1; }
}

__global__ __launch_bounds__(NT, 2) void varlen_attn_pipe(
    const float* __restrict__ qg, const float* __restrict__ kg, const float* __restrict__ vg,
    const int* __restrict__ cuq, const int* __restrict__ cuk,
    float* __restrict__ out, int T, int ncu)
{
    extern __shared__ char smc[];
    const uint32_t sb = s2u(smc);
    int* kseg = (int*)(smc + B_KSEG);
    int* cus  = (int*)(smc + B_CUS);

    const int tid  = threadIdx.x;
    const int lane = tid & 31;
    const int g    = lane >> 2;
    const int tig  = lane & 3;
    const int h  = blockIdx.y;
    const int q0 = blockIdx.x * BQ;

    const uint32_t lane_off = (((lane & 7) * 68 + 4 * (lane >> 3)) << 2);
    const int src0 = (lane & ~3) | (tig >> 1);
    const int src1 = src0 + 2;

    if (tid < ncu) cus[tid] = cuk[tid];
    __syncthreads();

    const int w = tid >> 5;
    const int t0g = q0 + w * 16 + g;
    const int t1g = t0g + 8;
    int qs0 = 0, qs1 = 0, sfirst = 0, slast = 0;
    {
        const int tl = min(q0 + BQ - 1, T - 1);
        for (int i = 1; i < ncu - 1; i++) {
            int c = cus[i];
            qs0 += (c <= t0g); qs1 += (c <= t1g);
            sfirst += (c <= q0); slast += (c <= tl);
        }
    }
    const int kbeg = cus[sfirst];
    const int kend = cus[slast + 1];
    const int kt0 = (kbeg / BK) * BK;

    // ---- prologue: issue cp.async for tile 0 into buf 0 ----
    {
        #pragma unroll
        for (int i = 0; i < 4; i++) {
            int idx = tid + i * NT;
            int r = idx >> 4, c4 = idx & 15;
            size_t gb = (size_t)(kt0 + r) * (HN * DD) + h * DD + c4 * 4;
            uint32_t so = (uint32_t)((r * 68 + c4 * 4) << 2);
            cpasync16(sb + B_K0 + so, kg + gb);
            cpasync16(sb + B_V0 + so, vg + gb);
        }
        CP_COMMIT();
    }

    // ---- Q fragments (registers, whole block) ----
    uint32_t qf[8][4];
    {
        const float* qp0 = qg + (size_t)t0g * (HN * DD) + h * DD;
        const float* qp1 = qg + (size_t)t1g * (HN * DD) + h * DD;
        #pragma unroll
        for (int ks = 0; ks < 8; ks++) {
            int d = ks * 8 + tig;
            qf[ks][0] = f2tf(qp0[d] * QSCALE);
            qf[ks][1] = f2tf(qp1[d] * QSCALE);
            qf[ks][2] = f2tf(qp0[d + 4] * QSCALE);
            qf[ks][3] = f2tf(qp1[d + 4] * QSCALE);
        }
    }

    float oacc[8][4];
    #pragma unroll
    for (int n = 0; n < 8; n++)
        #pragma unroll
        for (int j = 0; j < 4; j++) oacc[n][j] = 0.f;
    float l0 = 0.f, l1 = 0.f;

    int cur = 0;
    for (int kt = kt0; kt < kend; kt += BK, cur ^= 1) {
        const uint32_t kb = cur ? B_K1 : B_K0;
        const uint32_t vb = cur ? B_V1 : B_V0;

        CP_WAIT0();
        __syncthreads();   // tile ready + all readers of the other buffer done

        // ---- issue next tile into alternate buffer ----
        {
            int ktn = kt + BK;
            if (ktn < kend) {
                uint32_t kbn = cur ? B_K0 : B_K1;
                uint32_t vbn = cur ? B_V0 : B_V1;
                #pragma unroll
                for (int i = 0; i < 4; i++) {
                    int idx = tid + i * NT;
                    int r = idx >> 4, c4 = idx & 15;
                    size_t gb = (size_t)(ktn + r) * (HN * DD) + h * DD + c4 * 4;
                    uint32_t so = (uint32_t)((r * 68 + c4 * 4) << 2);
                    cpasync16(sb + kbn + so, kg + gb);
                    cpasync16(sb + vbn + so, vg + gb);
                }
            }
            CP_COMMIT();
        }

        // ---- condition: K cvt in place, Vraw -> Vt (cvt + transpose), kseg ----
        #pragma unroll
        for (int i = 0; i < 4; i++) {
            int idx = tid + i * NT;
            {
                int r = idx >> 4, c4 = idx & 15;
                float4* p = (float4*)(smc + kb + ((r * 68 + c4 * 4) << 2));
                float4 kv = *p;
                kv.x = __uint_as_float(f2tf(kv.x));
                kv.y = __uint_as_float(f2tf(kv.y));
                kv.z = __uint_as_float(f2tf(kv.z));
                kv.w = __uint_as_float(f2tf(kv.w));
                *p = kv;
            }
            {
                int lo = idx & 3, mid = (idx >> 2) & 15, hi = idx >> 6;
                float4 vv = *(const float4*)(smc + vb + (((4 * hi + lo) * 68 + 4 * mid) << 2));
                vv.x = __uint_as_float(f2tf(vv.x));
                vv.y = __uint_as_float(f2tf(vv.y));
                vv.z = __uint_as_float(f2tf(vv.z));
                vv.w = __uint_as_float(f2tf(vv.w));
                trans4(vv, lo);
                *(float4*)(smc + B_VT + (((4 * mid + lo) * 68 + 4 * hi) << 2)) = vv;
            }
        }
        if (tid < BK) {
            int t = kt + tid;
            int s = 0;
            for (int i = 1; i < ncu - 1; i++) s += (cus[i] <= t);
            kseg[tid] = s;
        }
        __syncthreads();

        // ---- S = Q K^T ----
        float sacc[8][4];
        #pragma unroll
        for (int n = 0; n < 8; n++)
            #pragma unroll
            for (int j = 0; j < 4; j++) sacc[n][j] = 0.f;

        const uint32_t kb_lane = sb + kb + lane_off;
        #pragma unroll
        for (int n = 0; n < 8; n++) {
            #pragma unroll
            for (int kk = 0; kk < 4; kk++) {
                uint32_t b[4];
                ldsm4(b, kb_lane + n * 2176 + kk * 64);
                mma8(sacc[n], qf[2 * kk],     b[0], b[1]);
                mma8(sacc[n], qf[2 * kk + 1], b[2], b[3]);
            }
        }

        // ---- mask + exp2 + C-layout -> A-layout fragment shuffle (into sacc) ----
        #pragma unroll
        for (int j = 0; j < 8; j++) {
            int kc = j * 8 + 2 * tig;
            int2 ks2 = *(const int2*)&kseg[kc];
            float p00 = (ks2.x == qs0) ? ex2f(sacc[j][0]) : 0.f;
            float p01 = (ks2.y == qs0) ? ex2f(sacc[j][1]) : 0.f;
            float p10 = (ks2.x == qs1) ? ex2f(sacc[j][2]) : 0.f;
            float p11 = (ks2.y == qs1) ? ex2f(sacc[j][3]) : 0.f;
            p00 = __uint_as_float(f2tf(p00));
            p01 = __uint_as_float(f2tf(p01));
            p10 = __uint_as_float(f2tf(p10));
            p11 = __uint_as_float(f2tf(p11));
            l0 += p00 + p01;
            l1 += p10 + p11;
            float e0 = __shfl_sync(0xffffffffu, p00, src0);
            float o0 = __shfl_sync(0xffffffffu, p01, src0);
            float e1 = __shfl_sync(0xffffffffu, p10, src0);
            float o1 = __shfl_sync(0xffffffffu, p11, src0);
            float e2 = __shfl_sync(0xffffffffu, p00, src1);
            float o2 = __shfl_sync(0xffffffffu, p01, src1);
            float e3 = __shfl_sync(0xffffffffu, p10, src1);
            float o3 = __shfl_sync(0xffffffffu, p11, src1);
            sacc[j][0] = (tig & 1) ? o0 : e0;   // A[g][tig]
            sacc[j][1] = (tig & 1) ? o1 : e1;   // A[g+8][tig]
            sacc[j][2] = (tig & 1) ? o2 : e2;   // A[g][tig+4]
            sacc[j][3] = (tig & 1) ? o3 : e3;   // A[g+8][tig+4]
        }

        // ---- O += P V ----
        const uint32_t vt_lane = sb + B_VT + lane_off;
        #pragma unroll
        for (int kk = 0; kk < 4; kk++) {
            #pragma unroll
            for (int n = 0; n < 8; n++) {
                uint32_t b[4];
                ldsm4(b, vt_lane + n * 2176 + kk * 64);
                mma8(oacc[n], (const uint32_t*)sacc[2 * kk],     b[0], b[1]);
                mma8(oacc[n], (const uint32_t*)sacc[2 * kk + 1], b[2], b[3]);
            }
        }
    }

    // ---- epilogue ----
    l0 += __shfl_xor_sync(0xffffffffu, l0, 1);
    l0 += __shfl_xor_sync(0xffffffffu, l0, 2);
    l1 += __shfl_xor_sync(0xffffffffu, l1, 1);
    l1 += __shfl_xor_sync(0xffffffffu, l1, 2);
    float i0 = 1.f / l0;
    float i1 = 1.f / l1;

    float* o0 = out + (size_t)t0g * (HN * DD) + h * DD;
    float* o1 = out + (size_t)t1g * (HN * DD) + h * DD;
    #pragma unroll
    for (int n = 0; n < 8; n++) {
        int c = n * 8 + 2 * tig;
        *(float2*)(o0 + c) = make_float2(oacc[n][0] * i0, oacc[n][1] * i0);
        *(float2*)(o1 + c) = make_float2(oacc[n][2] * i1, oacc[n][3] * i1);
    }
}

extern "C" void kernel_launch(void* const* d_in, const int* in_sizes, int n_in,
                              void* d_out, int out_size)
{
    const float* q = (const float*)d_in[0];
    const float* k = (const float*)d_in[1];
    const float* v = (const float*)d_in[2];
    const int* cuq = (const int*)d_in[3];
    const int* cuk = (const int*)d_in[4];

    int T = in_sizes[0] / (HN * DD);
    int ncu = in_sizes[3];

    cudaFuncSetAttribute(varlen_attn_pipe,
                         cudaFuncAttributeMaxDynamicSharedMemorySize, SMEM_BYTES);

    dim3 grid((T + BQ - 1) / BQ, HN);
    varlen_attn_pipe<<<grid, NT, SMEM_BYTES>>>(q, k, v, cuq, cuk, (float*)d_out, T, ncu);
}

// round 6
// speedup vs baseline: 2.0572x; 2.0572x over previous
#include <cuda_runtime.h>
#include <cuda_fp16.h>
#include <cstdint>

#define HN 16
#define DD 64
#define BQ 128
#define BK 64
#define NT 256
#define QSCALE 0.1803368801111f   // (1/8) * log2(e)

// smem BYTE offsets
#define B_KH   0            // K fp16 [64][72] halves = 9216B
#define B_VH   9216         // V fp16 [64][72] halves = 9216B
#define B_KSEG 18432        // 64 ints
#define B_CUS  18688        // 64 ints
#define SMEM_BYTES 18944

__device__ __forceinline__ float ex2f(float x) {
    float y; asm("ex2.approx.ftz.f32 %0, %1;" : "=f"(y) : "f"(x)); return y;
}
__device__ __forceinline__ uint32_t packh2(float lo, float hi) {
    half2 h = __floats2half2_rn(lo, hi);
    return *(uint32_t*)&h;
}
__device__ __forceinline__ void mma16(float* c, const uint32_t* a, uint32_t b0, uint32_t b1) {
    asm volatile("mma.sync.aligned.m16n8k16.row.col.f32.f16.f16.f32 "
                 "{%0,%1,%2,%3}, {%4,%5,%6,%7}, {%8,%9}, {%0,%1,%2,%3};"
                 : "+f"(c[0]), "+f"(c[1]), "+f"(c[2]), "+f"(c[3])
                 : "r"(a[0]), "r"(a[1]), "r"(a[2]), "r"(a[3]), "r"(b0), "r"(b1));
}
__device__ __forceinline__ void ldsm4(uint32_t* r, uint32_t addr) {
    asm volatile("ldmatrix.sync.aligned.m8n8.x4.shared.b16 {%0,%1,%2,%3}, [%4];"
                 : "=r"(r[0]), "=r"(r[1]), "=r"(r[2]), "=r"(r[3]) : "r"(addr));
}
__device__ __forceinline__ void ldsm4t(uint32_t* r, uint32_t addr) {
    asm volatile("ldmatrix.sync.aligned.m8n8.x4.trans.shared.b16 {%0,%1,%2,%3}, [%4];"
                 : "=r"(r[0]), "=r"(r[1]), "=r"(r[2]), "=r"(r[3]) : "r"(addr));
}
__device__ __forceinline__ uint32_t s2u(const void* p) {
    uint32_t a;
    asm("{ .reg .u64 t; cvta.to.shared.u64 t, %1; cvt.u32.u64 %0, t; }" : "=r"(a) : "l"(p));
    return a;
}

__global__ __launch_bounds__(NT, 2) void varlen_attn_h2(
    const float* __restrict__ qg, const float* __restrict__ kg, const float* __restrict__ vg,
    const int* __restrict__ cuq, const int* __restrict__ cuk,
    float* __restrict__ out, int T, int ncu)
{
    extern __shared__ char smc[];
    const uint32_t sb = s2u(smc);
    int* kseg = (int*)(smc + B_KSEG);
    int* cus  = (int*)(smc + B_CUS);

    const int tid  = threadIdx.x;
    const int w    = tid >> 5;
    const int lane = tid & 31;
    const int g    = lane >> 2;
    const int tig  = lane & 3;
    const int h  = blockIdx.y;
    const int q0 = blockIdx.x * BQ;

    // per-lane ldmatrix base: group j = lane>>3; row-in-matrix = lane&7
    // addr = base + ((lane&7) + 8*(j&1))*144 + (j>>1)*16
    const uint32_t lmoff = (uint32_t)(((lane & 7) + 8 * ((lane >> 3) & 1)) * 144 + (lane >> 4) * 16);
    const uint32_t klane = sb + B_KH + lmoff;
    const uint32_t vlane = sb + B_VH + lmoff;

    if (tid < ncu) cus[tid] = cuk[tid];
    __syncthreads();

    const int t0g = q0 + w * 16 + g;
    const int t1g = t0g + 8;
    int qs0 = 0, qs1 = 0, sfirst = 0, slast = 0;
    {
        const int tl = min(q0 + BQ - 1, T - 1);
        for (int i = 1; i < ncu - 1; i++) {
            int c = cus[i];
            qs0 += (c <= t0g); qs1 += (c <= t1g);
            sfirst += (c <= q0); slast += (c <= tl);
        }
    }
    const int kbeg = cus[sfirst];
    const int kend = cus[slast + 1];

    // ---- Q fragments: fp16 m16n8k16 A-layout, 4 chunks of k16 ----
    uint32_t qaf[4][4];
    {
        const float* qp0 = qg + (size_t)t0g * (HN * DD) + h * DD;
        const float* qp1 = qg + (size_t)t1g * (HN * DD) + h * DD;
        #pragma unroll
        for (int kk = 0; kk < 4; kk++) {
            int d0 = kk * 16 + 2 * tig;
            float2 a = *(const float2*)(qp0 + d0);
            float2 b = *(const float2*)(qp1 + d0);
            float2 c = *(const float2*)(qp0 + d0 + 8);
            float2 d = *(const float2*)(qp1 + d0 + 8);
            qaf[kk][0] = packh2(a.x * QSCALE, a.y * QSCALE);
            qaf[kk][1] = packh2(b.x * QSCALE, b.y * QSCALE);
            qaf[kk][2] = packh2(c.x * QSCALE, c.y * QSCALE);
            qaf[kk][3] = packh2(d.x * QSCALE, d.y * QSCALE);
        }
    }

    float oacc[8][4];
    #pragma unroll
    for (int n = 0; n < 8; n++)
        #pragma unroll
        for (int j = 0; j < 4; j++) oacc[n][j] = 0.f;
    float l0 = 0.f, l1 = 0.f;

    for (int kt = (kbeg / BK) * BK; kt < kend; kt += BK) {
        __syncthreads();   // previous tile's readers done

        // ---- load K,V tile: LDG fp32 -> cvt fp16 -> STS (no transpose needed) ----
        #pragma unroll
        for (int i = 0; i < 4; i++) {
            int idx = tid + i * NT;           // 0..1023
            int r = idx >> 4, c4 = idx & 15;  // row, 4-col chunk
            size_t gb = (size_t)(kt + r) * (HN * DD) + h * DD + c4 * 4;
            float4 kv = *(const float4*)(kg + gb);
            float4 vv = *(const float4*)(vg + gb);
            uint32_t so = (uint32_t)((r * 72 + c4 * 4) * 2);
            uint2 kp = make_uint2(packh2(kv.x, kv.y), packh2(kv.z, kv.w));
            uint2 vp = make_uint2(packh2(vv.x, vv.y), packh2(vv.z, vv.w));
            *(uint2*)(smc + B_KH + so) = kp;
            *(uint2*)(smc + B_VH + so) = vp;
        }
        if (tid < BK) {
            int t = kt + tid;
            int s = 0;
            for (int i = 1; i < ncu - 1; i++) s += (cus[i] <= t);
            kseg[tid] = s;
        }
        __syncthreads();

        // ---- S = Q K^T : B-frags via plain ldmatrix on K[k][d] ----
        float sacc[8][4];
        #pragma unroll
        for (int n = 0; n < 8; n++)
            #pragma unroll
            for (int j = 0; j < 4; j++) sacc[n][j] = 0.f;

        #pragma unroll
        for (int kk = 0; kk < 4; kk++) {
            #pragma unroll
            for (int np = 0; np < 4; np++) {
                uint32_t kf[4];
                ldsm4(kf, klane + np * 2304 + kk * 32);
                mma16(sacc[2 * np],     qaf[kk], kf[0], kf[2]);
                mma16(sacc[2 * np + 1], qaf[kk], kf[1], kf[3]);
            }
        }

        // ---- mask + exp2 + pack to fp16 A-fragments (no shuffles needed) ----
        uint32_t af[4][4];
        #pragma unroll
        for (int kk = 0; kk < 4; kk++) {
            #pragma unroll
            for (int half_ = 0; half_ < 2; half_++) {
                int j = 2 * kk + half_;
                int kc = j * 8 + 2 * tig;
                int2 ks2 = *(const int2*)&kseg[kc];
                float p00 = (ks2.x == qs0) ? ex2f(sacc[j][0]) : 0.f;
                float p01 = (ks2.y == qs0) ? ex2f(sacc[j][1]) : 0.f;
                float p10 = (ks2.x == qs1) ? ex2f(sacc[j][2]) : 0.f;
                float p11 = (ks2.y == qs1) ? ex2f(sacc[j][3]) : 0.f;
                l0 += p00 + p01;
                l1 += p10 + p11;
                af[kk][2 * half_ + 0] = packh2(p00, p01);
                af[kk][2 * half_ + 1] = packh2(p10, p11);
            }
            // reorder: A-frag = {j0:(g,..),(g+8,..), j1:(g,..),(g+8,..)}
            uint32_t t1 = af[kk][1], t2 = af[kk][2];
            af[kk][1] = t2; af[kk][2] = t1;
        }
        // af[kk] = {lowk(g), lowk(g+8), highk(g), highk(g+8)} -> need {a0,a1,a2,a3} =
        // {(g,klow),(g+8,klow),(g,khigh),(g+8,khigh)} : fix ordering
        #pragma unroll
        for (int kk = 0; kk < 4; kk++) {
            uint32_t t1 = af[kk][1], t2 = af[kk][2];
            af[kk][1] = t2; af[kk][2] = t1;
        }

        // ---- O += P V : B-frags via ldmatrix.trans on V[k][d] ----
        #pragma unroll
        for (int kk = 0; kk < 4; kk++) {
            #pragma unroll
            for (int np = 0; np < 4; np++) {
                uint32_t vf[4];
                ldsm4t(vf, vlane + kk * 2304 + np * 32);
                mma16(oacc[2 * np],     af[kk], vf[0], vf[1]);
                mma16(oacc[2 * np + 1], af[kk], vf[2], vf[3]);
            }
        }
    }

    // ---- epilogue ----
    l0 += __shfl_xor_sync(0xffffffffu, l0, 1);
    l0 += __shfl_xor_sync(0xffffffffu, l0, 2);
    l1 += __shfl_xor_sync(0xffffffffu, l1, 1);
    l1 += __shfl_xor_sync(0xffffffffu, l1, 2);
    float i0 = 1.f / l0;
    float i1 = 1.f / l1;

    float* o0 = out + (size_t)t0g * (HN * DD) + h * DD;
    float* o1 = out + (size_t)t1g * (HN * DD) + h * DD;
    #pragma unroll
    for (int n = 0; n < 8; n++) {
        int c = n * 8 + 2 * tig;
        *(float2*)(o0 + c) = make_float2(oacc[n][0] * i0, oacc[n][1] * i0);
        *(float2*)(o1 + c) = make_float2(oacc[n][2] * i1, oacc[n][3] * i1);
    }
}

extern "C" void kernel_launch(void* const* d_in, const int* in_sizes, int n_in,
                              void* d_out, int out_size)
{
    const float* q = (const float*)d_in[0];
    const float* k = (const float*)d_in[1];
    const float* v = (const float*)d_in[2];
    const int* cuq = (const int*)d_in[3];
    const int* cuk = (const int*)d_in[4];

    int T = in_sizes[0] / (HN * DD);
    int ncu = in_sizes[3];

    cudaFuncSetAttribute(varlen_attn_h2,
                         cudaFuncAttributeMaxDynamicSharedMemorySize, SMEM_BYTES);

    dim3 grid((T + BQ - 1) / BQ, HN);
    varlen_attn_h2<<<grid, NT, SMEM_BYTES>>>(q, k, v, cuq, cuk, (float*)d_out, T, ncu);
}